// round 12
// baseline (speedup 1.0000x reference)
#include <cuda_runtime.h>
#include <cuda_fp16.h>
#include <cstdint>

// Problem constants
#define Nn 20000
#define Ee 320000
#define Bb 2
#define INF_DIM 32
#define HIDD 64
#define HEADS 4
#define OUTD 8
#define SLOPE 0.2f

#define NB (Nn*Bb)              // 40000
#define FTC (HEADS*HIDD)        // 256

// Scratch (device globals)
__device__ __align__(16) float g_x[NB*HIDD];
__device__ __align__(16) __half g_fth[(size_t)NB*FTC];   // ft in fp16
__device__ __align__(16) float g_res[NB*HIDD];
__device__ float g_el[NB*HEADS];   // [(node*2+b)*4 + h]
__device__ float g_er[NB*HEADS];
__device__ float g_P[HIDD*8];      // [k*8 + q], q<4: Pl, q>=4: Pr
__device__ int g_deg[Nn];
__device__ int g_rowptr[Nn];
__device__ int g_col[Ee];
__device__ int g_rank[Ee];
__device__ int g_total;

// ---- packed f32x2 helpers (sm_103a FFMA2) ----
__device__ __forceinline__ uint64_t pk2(float lo, float hi) {
    uint64_t r; asm("mov.b64 %0, {%1,%2};" : "=l"(r) : "f"(lo), "f"(hi)); return r;
}
__device__ __forceinline__ void fma2(uint64_t& acc, uint64_t a, uint64_t b) {
    asm("fma.rn.f32x2 %0, %1, %2, %0;" : "+l"(acc) : "l"(a), "l"(b));
}
__device__ __forceinline__ float2 upk(uint64_t v) {
    float2 r; asm("mov.b64 {%0,%1}, %2;" : "=f"(r.x), "=f"(r.y) : "l"(v)); return r;
}

// ---------------- CSR build ----------------
__global__ void zero_k() {
    int idx = blockIdx.x * blockDim.x + threadIdx.x;
    if (idx < Nn) g_deg[idx] = 0;
    if (idx == 0) g_total = 0;
}

__global__ void hist_k(const int* __restrict__ ei) {
    int idx = blockIdx.x * blockDim.x + threadIdx.x;
    if (idx < Ee) g_rank[idx] = atomicAdd(&g_deg[ei[Ee + idx]], 1);
}

__global__ void alloc_k() {
    int idx = blockIdx.x * blockDim.x + threadIdx.x;
    int lane = threadIdx.x & 31;
    int d = (idx < Nn) ? g_deg[idx] : 0;
    int incl = d;
#pragma unroll
    for (int o = 1; o < 32; o <<= 1) {
        int t = __shfl_up_sync(0xffffffffu, incl, o);
        if (lane >= o) incl += t;
    }
    int wtot = __shfl_sync(0xffffffffu, incl, 31);
    int base = 0;
    if (lane == 0) base = atomicAdd(&g_total, wtot);
    base = __shfl_sync(0xffffffffu, base, 0);
    if (idx < Nn) g_rowptr[idx] = base + incl - d;
}

__global__ void fill_k(const int* __restrict__ ei) {
    int idx = blockIdx.x * blockDim.x + threadIdx.x;
    if (idx >= Ee) return;
    int d = ei[Ee + idx];
    g_col[g_rowptr[d] + g_rank[idx]] = ei[idx];
}

// ---------------- P = reshape(W_gat)[k, h*64+d] @ a_{l,r}[h, d] ----------------
__global__ void proj_k(const float* __restrict__ W_gat, const float* __restrict__ a_l,
                       const float* __restrict__ a_r) {
    int t = threadIdx.x;          // 512 threads
    int k = t >> 3, q = t & 7;
    int h = q & 3;
    const float* a = (q < 4) ? a_l : a_r;
    float s = 0.f;
#pragma unroll
    for (int d = 0; d < HIDD; d++)
        s += W_gat[k*FTC + h*HIDD + d] * a[h*HIDD + d];
    g_P[k*8 + q] = s;
}

// ---------------- encoder ----------------
__global__ void enc_k(const float* __restrict__ h, const float* __restrict__ W_enc,
                      const float* __restrict__ b_enc) {
    int idx = blockIdx.x * blockDim.x + threadIdx.x;
    if (idx >= NB*HIDD) return;
    int d  = idx & 63;
    int nb = idx >> 6;
    int n = nb >> 1, b = nb & 1;
    const float* hr = &h[((size_t)b*Nn + n)*INF_DIM];
    float acc = b_enc[d];
#pragma unroll
    for (int k = 0; k < INF_DIM; k++) acc += hr[k] * W_enc[k*HIDD + d];
    g_x[idx] = acc;
}

// ---------------- ft = x @ W_gat (fp16), res = x @ W_res + b_res, el/er = x @ P ----------------
#define FTROWS 32
#define XPAD 17             // u64 pitch (pad)
__global__ void ft_k(const float* __restrict__ W_gat,
                     const float* __restrict__ W_res, const float* __restrict__ b_res) {
    __shared__ uint64_t xs2[HIDD * XPAD];
    __shared__ float Ps[HIDD * 8];
    int t = threadIdx.x;
    int nb0 = blockIdx.x * FTROWS;

    {
        float* xf = (float*)xs2;
        for (int i = t; i < FTROWS*HIDD; i += 256) {
            int row = i >> 6, k = i & 63;
            xf[k*(2*XPAD) + row] = g_x[(size_t)(nb0 + row)*HIDD + k];
        }
        for (int i = t; i < HIDD*8; i += 256) Ps[i] = g_P[i];
    }
    __syncthreads();

    // main GEMM: col-quad x 4 row-pairs (1 LDG.128 + 4 LDS.64 + 16 FFMA2 per k)
    {
        int cq = t & 63;
        int rh = t >> 6;
        uint64_t acc[4][4];
#pragma unroll
        for (int c = 0; c < 4; c++)
#pragma unroll
            for (int r = 0; r < 4; r++) acc[c][r] = 0ull;

        for (int k = 0; k < HIDD; k++) {
            float4 w = *(const float4*)&W_gat[k*FTC + cq*4];
            uint64_t w0 = pk2(w.x, w.x);
            uint64_t w1 = pk2(w.y, w.y);
            uint64_t w2 = pk2(w.z, w.z);
            uint64_t w3 = pk2(w.w, w.w);
            const uint64_t* xr = &xs2[k*XPAD + rh*4];
#pragma unroll
            for (int r = 0; r < 4; r++) {
                uint64_t xv = xr[r];
                fma2(acc[0][r], xv, w0);
                fma2(acc[1][r], xv, w1);
                fma2(acc[2][r], xv, w2);
                fma2(acc[3][r], xv, w3);
            }
        }
#pragma unroll
        for (int r = 0; r < 4; r++) {
            float2 v0 = upk(acc[0][r]);
            float2 v1 = upk(acc[1][r]);
            float2 v2 = upk(acc[2][r]);
            float2 v3 = upk(acc[3][r]);
            int rp = rh*4 + r;
            __half2 e0 = __floats2half2_rn(v0.x, v1.x);
            __half2 e1 = __floats2half2_rn(v2.x, v3.x);
            __half2 o0 = __floats2half2_rn(v0.y, v1.y);
            __half2 o1 = __floats2half2_rn(v2.y, v3.y);
            *(uint2*)&g_fth[((size_t)(nb0 + 2*rp))*FTC + cq*4]     = make_uint2(
                *(unsigned*)&e0, *(unsigned*)&e1);
            *(uint2*)&g_fth[((size_t)(nb0 + 2*rp + 1))*FTC + cq*4] = make_uint2(
                *(unsigned*)&o0, *(unsigned*)&o1);
        }
    }

    // res: thread owns col pair (2cr, 2cr+1), 2 row-pairs
    {
        int cr = t & 31;
        int rr = t >> 5;
        float2 bb = *(const float2*)&b_res[cr*2];
        uint64_t a0[2], a1[2];
        a0[0] = pk2(bb.x, bb.x); a0[1] = a0[0];
        a1[0] = pk2(bb.y, bb.y); a1[1] = a1[0];
        for (int k = 0; k < HIDD; k++) {
            float2 w = *(const float2*)&W_res[k*HIDD + cr*2];
            uint64_t w0 = pk2(w.x, w.x);
            uint64_t w1 = pk2(w.y, w.y);
            const uint64_t* xr = &xs2[k*XPAD + rr*2];
            fma2(a0[0], xr[0], w0); fma2(a1[0], xr[0], w1);
            fma2(a0[1], xr[1], w0); fma2(a1[1], xr[1], w1);
        }
#pragma unroll
        for (int i = 0; i < 2; i++) {
            float2 va = upk(a0[i]);
            float2 vb = upk(a1[i]);
            int rp = rr*2 + i;
            *(float2*)&g_res[(size_t)(nb0 + 2*rp)*HIDD + cr*2]     = make_float2(va.x, vb.x);
            *(float2*)&g_res[(size_t)(nb0 + 2*rp + 1)*HIDD + cr*2] = make_float2(va.y, vb.y);
        }
    }

    // el/er
    {
        int r = t >> 3, q = t & 7;
        const float* xf = (const float*)xs2;
        float s = 0.f;
        for (int k = 0; k < HIDD; k++)
            s += xf[k*(2*XPAD) + r] * Ps[k*8 + q];
        int nb = nb0 + r;
        if (q < 4) g_el[nb*4 + q]       = s;
        else       g_er[nb*4 + (q - 4)] = s;
    }
}

// ---------------- fused node-centric GAT aggregation + update (+ optional decoder) ----------------
// ONE WARP PER (node, batch). Lane owns (head = lane>>3, dims (lane&7)*8..+8);
// a 256-col fp16 row = 512B = 32 x LDG.128, so one load per lane per edge.
// e-values batched 32-per-window (lane = slot + head), consumed via per-lane-indexed shfl.
__global__ void node_agg_k(const float* __restrict__ b_gat,
                           const float* __restrict__ W_dec, const float* __restrict__ b_dec,
                           float* __restrict__ out, int last) {
    int gw = (blockIdx.x * blockDim.x + threadIdx.x) >> 5;
    int lane = threadIdx.x & 31;
    if (gw >= NB) return;
    int w = gw >> 1, b = gw & 1;
    int beg = g_rowptr[w];
    int end = beg + g_deg[w];

    int hq = lane >> 3;     // head owned by this lane
    int dq = lane & 7;      // dim-octet within head (also edge-slot in e-batch role)

    float er_mine = g_er[w*8 + b*4 + hq];

    float acc[8];
#pragma unroll
    for (int i = 0; i < 8; i++) acc[i] = 0.f;
    float zpart = 0.f;

    for (int i0 = beg; i0 < end; i0 += 32) {
        int nE = end - i0; if (nE > 32) nE = 32;
        int sj = (i0 + lane < end) ? g_col[i0 + lane] : 0;

        // e-batch: lane computes e for edges j = dq + 8k (k=0..3), its own head hq
        float ereg[4];
#pragma unroll
        for (int k = 0; k < 4; k++) {
            int j = dq + 8*k;
            int s = __shfl_sync(0xffffffffu, sj, j);
            float e = 0.f;
            if (j < nE) {
                float v = g_el[s*8 + b*4 + hq] + er_mine;
                v = v > 0.f ? v : SLOPE * v;
                e = __expf(v);
            }
            ereg[k] = e;
            zpart += e;
        }

        // FMA loop: 4-edge chunks, predicated (no break inside chunk -> 4 LDGs in flight)
        for (int j0 = 0; j0 < nE; j0 += 4) {
#pragma unroll
            for (int jj = 0; jj < 4; jj++) {
                int j = j0 + jj;
                int s = __shfl_sync(0xffffffffu, sj, j & 31);
                float a = __shfl_sync(0xffffffffu, ereg[(j >> 3) & 3], hq*8 + (j & 7));
                if (j >= nE) a = 0.f;
                const uint4* f = (const uint4*)&g_fth[((size_t)(s*2 + b))*FTC];
                uint4 u = f[lane];
                float2 p0 = __half22float2(*(__half2*)&u.x);
                float2 p1 = __half22float2(*(__half2*)&u.y);
                float2 p2 = __half22float2(*(__half2*)&u.z);
                float2 p3 = __half22float2(*(__half2*)&u.w);
                acc[0] += a*p0.x; acc[1] += a*p0.y;
                acc[2] += a*p1.x; acc[3] += a*p1.y;
                acc[4] += a*p2.x; acc[5] += a*p2.y;
                acc[6] += a*p3.x; acc[7] += a*p3.y;
            }
        }
    }

    // z reduce within 8-lane head group
    zpart += __shfl_xor_sync(0xffffffffu, zpart, 1);
    zpart += __shfl_xor_sync(0xffffffffu, zpart, 2);
    zpart += __shfl_xor_sync(0xffffffffu, zpart, 4);
    float rz = (zpart > 0.f) ? 0.25f / zpart : 0.f;

    // normalize + fold 0.25*b_gat (own head slice), then cross-head reduce
    int dbase = dq * 8;
    float4 bga = *(const float4*)&b_gat[hq*64 + dbase];
    float4 bgb = *(const float4*)&b_gat[hq*64 + dbase + 4];
    acc[0] = acc[0]*rz + 0.25f*bga.x;
    acc[1] = acc[1]*rz + 0.25f*bga.y;
    acc[2] = acc[2]*rz + 0.25f*bga.z;
    acc[3] = acc[3]*rz + 0.25f*bga.w;
    acc[4] = acc[4]*rz + 0.25f*bgb.x;
    acc[5] = acc[5]*rz + 0.25f*bgb.y;
    acc[6] = acc[6]*rz + 0.25f*bgb.z;
    acc[7] = acc[7]*rz + 0.25f*bgb.w;
#pragma unroll
    for (int o = 8; o <= 16; o <<= 1)
#pragma unroll
        for (int i = 0; i < 8; i++)
            acc[i] += __shfl_xor_sync(0xffffffffu, acc[i], o);
    // acc[] now = head-mean agg + mean bias, for global dims dbase..dbase+8 (replicated x4)

    // + res + ELU
    float4 rv0 = *(const float4*)&g_res[((size_t)(w*2 + b))*HIDD + dbase];
    float4 rv1 = *(const float4*)&g_res[((size_t)(w*2 + b))*HIDD + dbase + 4];
    float xv[8];
    xv[0] = acc[0] + rv0.x; xv[1] = acc[1] + rv0.y;
    xv[2] = acc[2] + rv0.z; xv[3] = acc[3] + rv0.w;
    xv[4] = acc[4] + rv1.x; xv[5] = acc[5] + rv1.y;
    xv[6] = acc[6] + rv1.z; xv[7] = acc[7] + rv1.w;
#pragma unroll
    for (int i = 0; i < 8; i++)
        xv[i] = xv[i] > 0.f ? xv[i] : expm1f(xv[i]);

    if (!last) {
        if (hq == 0) {
            float* xp = &g_x[((size_t)(w*2 + b))*HIDD + dbase];
            *(float4*)&xp[0] = make_float4(xv[0], xv[1], xv[2], xv[3]);
            *(float4*)&xp[4] = make_float4(xv[4], xv[5], xv[6], xv[7]);
        }
    } else {
        // fused decoder: lane computes out cols {2hq, 2hq+1} partial over dims dbase..+8
        float s0 = 0.f, s1 = 0.f;
#pragma unroll
        for (int i = 0; i < 8; i++) {
            float2 wd = *(const float2*)&W_dec[(dbase + i)*OUTD + hq*2];
            s0 += xv[i]*wd.x;
            s1 += xv[i]*wd.y;
        }
        s0 += __shfl_xor_sync(0xffffffffu, s0, 1);
        s1 += __shfl_xor_sync(0xffffffffu, s1, 1);
        s0 += __shfl_xor_sync(0xffffffffu, s0, 2);
        s1 += __shfl_xor_sync(0xffffffffu, s1, 2);
        s0 += __shfl_xor_sync(0xffffffffu, s0, 4);
        s1 += __shfl_xor_sync(0xffffffffu, s1, 4);
        if (dq == 0) {
            float2 bd = *(const float2*)&b_dec[hq*2];
            *(float2*)&out[((size_t)b*Nn + w)*OUTD + hq*2] = make_float2(s0 + bd.x, s1 + bd.y);
        }
    }
}

extern "C" void kernel_launch(void* const* d_in, const int* in_sizes, int n_in,
                              void* d_out, int out_size) {
    const float* h     = (const float*)d_in[0];
    const int*   ei    = (const int*)  d_in[1];
    const float* W_enc = (const float*)d_in[2];
    const float* b_enc = (const float*)d_in[3];
    const float* W_gat = (const float*)d_in[4];
    const float* a_l   = (const float*)d_in[5];
    const float* a_r   = (const float*)d_in[6];
    const float* b_gat = (const float*)d_in[7];
    const float* W_res = (const float*)d_in[8];
    const float* b_res = (const float*)d_in[9];
    const float* W_dec = (const float*)d_in[10];
    const float* b_dec = (const float*)d_in[11];
    float* out = (float*)d_out;

    // CSR build (every call; graph-replay safe)
    zero_k<<<(Nn + 255)/256, 256>>>();
    hist_k<<<(Ee + 255)/256, 256>>>(ei);
    alloc_k<<<(Nn + 255)/256, 256>>>();
    fill_k<<<(Ee + 255)/256, 256>>>(ei);

    proj_k<<<1, 512>>>(W_gat, a_l, a_r);
    enc_k<<<(NB*HIDD + 255)/256, 256>>>(h, W_enc, b_enc);

    for (int it = 0; it < 2; ++it) {
        ft_k<<<NB/FTROWS, 256>>>(W_gat, W_res, b_res);
        node_agg_k<<<(NB*32 + 255)/256, 256>>>(b_gat, W_dec, b_dec, out, it == 1);
    }
}